// round 4
// baseline (speedup 1.0000x reference)
#include <cuda_runtime.h>

// Scratch accumulator — __device__ global (no allocation).
__device__ double g_acc;

__global__ void zero_acc_kernel() {
    g_acc = 0.0;
}

// Each float4 covers TWO 2D points (x0,y0,x1,y1).
__global__ void __launch_bounds__(256) dist_sum_kernel(
    const float4* __restrict__ preds,
    const float4* __restrict__ targets,
    long long n4)
{
    float local = 0.0f;
    long long idx    = (long long)blockIdx.x * blockDim.x + threadIdx.x;
    long long stride = (long long)gridDim.x * blockDim.x;

    // Grid-stride, unrolled x4 -> 8 independent 16B streaming loads per iter.
    long long i = idx;
    #pragma unroll 1
    for (; i + 3 * stride < n4; i += 4 * stride) {
        float4 a0 = __ldcs(&preds[i]);
        float4 a1 = __ldcs(&preds[i + stride]);
        float4 a2 = __ldcs(&preds[i + 2 * stride]);
        float4 a3 = __ldcs(&preds[i + 3 * stride]);
        float4 b0 = __ldcs(&targets[i]);
        float4 b1 = __ldcs(&targets[i + stride]);
        float4 b2 = __ldcs(&targets[i + 2 * stride]);
        float4 b3 = __ldcs(&targets[i + 3 * stride]);

        float dx, dy;
        dx = a0.x - b0.x; dy = a0.y - b0.y; local += sqrtf(fmaf(dx, dx, dy * dy));
        dx = a0.z - b0.z; dy = a0.w - b0.w; local += sqrtf(fmaf(dx, dx, dy * dy));
        dx = a1.x - b1.x; dy = a1.y - b1.y; local += sqrtf(fmaf(dx, dx, dy * dy));
        dx = a1.z - b1.z; dy = a1.w - b1.w; local += sqrtf(fmaf(dx, dx, dy * dy));
        dx = a2.x - b2.x; dy = a2.y - b2.y; local += sqrtf(fmaf(dx, dx, dy * dy));
        dx = a2.z - b2.z; dy = a2.w - b2.w; local += sqrtf(fmaf(dx, dx, dy * dy));
        dx = a3.x - b3.x; dy = a3.y - b3.y; local += sqrtf(fmaf(dx, dx, dy * dy));
        dx = a3.z - b3.z; dy = a3.w - b3.w; local += sqrtf(fmaf(dx, dx, dy * dy));
    }
    for (; i < n4; i += stride) {
        float4 a = __ldcs(&preds[i]);
        float4 b = __ldcs(&targets[i]);
        float dx0 = a.x - b.x, dy0 = a.y - b.y;
        float dx1 = a.z - b.z, dy1 = a.w - b.w;
        local += sqrtf(fmaf(dx0, dx0, dy0 * dy0));
        local += sqrtf(fmaf(dx1, dx1, dy1 * dy1));
    }

    // Warp reduce
    #pragma unroll
    for (int o = 16; o > 0; o >>= 1)
        local += __shfl_xor_sync(0xFFFFFFFFu, local, o);

    __shared__ float smem[8];
    int lane = threadIdx.x & 31;
    int warp = threadIdx.x >> 5;
    if (lane == 0) smem[warp] = local;
    __syncthreads();

    if (warp == 0) {
        local = (lane < (blockDim.x >> 5)) ? smem[lane] : 0.0f;
        #pragma unroll
        for (int o = 4; o > 0; o >>= 1)
            local += __shfl_xor_sync(0xFFFFFFFFu, local, o);
        if (lane == 0)
            atomicAdd(&g_acc, (double)local);
    }
}

__global__ void finalize_kernel(float* __restrict__ out, long long n_points) {
    out[0] = (float)(g_acc / (double)(n_points + 1));
}

extern "C" void kernel_launch(void* const* d_in, const int* in_sizes, int n_in,
                              void* d_out, int out_size)
{
    const float4* preds   = (const float4*)d_in[0];
    const float4* targets = (const float4*)d_in[1];
    float* out = (float*)d_out;

    long long n_elems  = (long long)in_sizes[0];   // N*2 floats
    long long n_points = n_elems / 2;              // N
    long long n4       = n_elems / 4;              // float4 groups (2 points each)

    zero_acc_kernel<<<1, 1>>>();

    const int threads = 256;
    int blocks = 148 * 16;  // 2368 blocks — full chip, deep MLP per SM
    dist_sum_kernel<<<blocks, threads>>>(preds, targets, n4);

    finalize_kernel<<<1, 1>>>(out, n_points);
}